// round 14
// baseline (speedup 1.0000x reference)
#include <cuda_runtime.h>
#include <cuda_bf16.h>
#include <cstdint>
#include <cstddef>

#define NE 8
#define NB 16384
#define ND 1024
#define NHH 512
#define NGH 128

#if defined(__CUDA_ARCH__) && (defined(__CUDA_ARCH_FEAT_SM103_ALL) || defined(__CUDA_ARCH_FEAT_SM100_ALL) || defined(__CUDA_ARCH_FEAT_SM101_ALL))
#define TC_OK 1
#else
#define TC_OK 0
#endif

// ---------------- device scratch ----------------
__device__ __align__(16) float g_tmpT[(size_t)NE * NHH * NHH];
__device__ __align__(16) float g_WcT[(size_t)NE * NHH * ND];      // f32 combined weight (K-major)
// Wp: per (e,kb) 64KB block = pre-swizzled SMEM image of the 512x(K=32) tf32 B tile
__device__ __align__(16) uint32_t g_Wp[(size_t)NE * NHH * ND];
__device__ __align__(16) float g_WoT[(size_t)NE * NHH * NHH];
__device__ __align__(16) float g_Wg1T[(size_t)NGH * ND];
__device__ __align__(16) float g_bc[NE * NHH];
__device__ __align__(16) float g_hidden[(size_t)NB * NGH];
__device__ __align__(16) float g_gate[NB * NE];

// ---------------- portable helpers ----------------
static __device__ __forceinline__ uint32_t smem_u32(const void* p) {
    uint32_t a;
    asm("{ .reg .u64 t; cvta.to.shared.u64 t, %1; cvt.u32.u64 %0, t; }" : "=r"(a) : "l"(p));
    return a;
}
static __device__ __forceinline__ float to_tf32(float x) {
    float r;
    asm("cvt.rna.tf32.f32 %0, %1;" : "=f"(r) : "f"(x));
    return r;
}
// split a,b into packed-bf16 hi word and lo word
static __device__ __forceinline__ void split2(float a, float b, uint32_t& hi, uint32_t& lo) {
    __nv_bfloat16 ha = __float2bfloat16(a), hb = __float2bfloat16(b);
    float la = a - __bfloat162float(ha), lb = b - __bfloat162float(hb);
    hi = (uint32_t)__bfloat16_as_ushort(ha) | ((uint32_t)__bfloat16_as_ushort(hb) << 16);
    __nv_bfloat16 lA = __float2bfloat16(la), lB = __float2bfloat16(lb);
    lo = (uint32_t)__bfloat16_as_ushort(lA) | ((uint32_t)__bfloat16_as_ushort(lB) << 16);
}

#if TC_OK
static __device__ __forceinline__ uint32_t elect_one() {
    uint32_t r;
    asm volatile("{ .reg .pred p; elect.sync _|p, 0xFFFFFFFF; selp.b32 %0,1,0,p; }" : "=r"(r));
    return r;
}
#define MBAR_INIT(a, c) asm volatile("mbarrier.init.shared.b64 [%0], %1;" ::"r"(a), "r"(c) : "memory")
#define MBAR_INVAL(a)   asm volatile("mbarrier.inval.shared.b64 [%0];" ::"r"(a) : "memory")
#define MBAR_EXPECT_TX(a, n) \
    asm volatile("mbarrier.arrive.expect_tx.shared.b64 _, [%0], %1;" ::"r"(a), "r"(n) : "memory")
#define MBAR_WAIT(a, ph) do { \
    uint32_t _m = (a), _p = (uint32_t)(ph), _d; \
    asm volatile("{ .reg .pred p; mbarrier.try_wait.parity.acquire.cta.shared::cta.b64 p, [%1], %2; selp.b32 %0,1,0,p; }" \
                 : "=r"(_d) : "r"(_m), "r"(_p) : "memory"); \
    if (!_d) { \
        asm volatile("{ .reg .pred P1; W%=: mbarrier.try_wait.parity.acquire.cta.shared::cta.b64 P1, [%0], %1, 0x989680; @P1 bra.uni D%=; bra.uni W%=; D%=: }" \
                     :: "r"(_m), "r"(_p) : "memory"); \
    } } while (0)
#define BULK_G2S(dst, src, bytes, mbar) \
    asm volatile("cp.async.bulk.shared::cluster.global.mbarrier::complete_tx::bytes [%0], [%1], %2, [%3];" \
                 :: "r"(dst), "l"(src), "r"(bytes), "r"(mbar) : "memory")
#define TC_ALLOC(sa, n)  asm volatile("tcgen05.alloc.cta_group::1.sync.aligned.shared::cta.b32 [%0], %1;" ::"r"(sa), "r"(n) : "memory")
#define TC_DEALLOC(t, n) asm volatile("tcgen05.dealloc.cta_group::1.sync.aligned.b32 %0, %1;" ::"r"(t), "r"(n))
#define TC_RELINQ()      asm volatile("tcgen05.relinquish_alloc_permit.cta_group::1.sync.aligned;")
#define TC_COMMIT(a)     asm volatile("tcgen05.commit.cta_group::1.mbarrier::arrive::one.shared::cluster.b64 [%0];" ::"r"(a) : "memory")
#define TC_WAIT_LD()     asm volatile("tcgen05.wait::ld.sync.aligned;" ::: "memory")
#define TC_FENCE_AFTER() asm volatile("tcgen05.fence::after_thread_sync;" ::: "memory")
#define FENCE_ASYNC()    asm volatile("fence.proxy.async.shared::cta;" ::: "memory")

static __device__ __forceinline__ void mma_tf32(uint32_t d, uint64_t ad, uint64_t bd,
                                                uint32_t idesc, uint32_t en) {
    asm volatile(
        "{ .reg .pred p; setp.ne.u32 p, %5, 0;\n\t"
        "tcgen05.mma.cta_group::1.kind::tf32 [%0], %1, %2, %3, {%4,%4,%4,%4}, p; }"
        :: "r"(d), "l"(ad), "l"(bd), "r"(idesc), "r"(0u), "r"(en) : "memory");
}
#define TC_LD_X32(r, a) \
    asm volatile("tcgen05.ld.sync.aligned.32x32b.x32.b32 " \
        "{%0,%1,%2,%3,%4,%5,%6,%7,%8,%9,%10,%11,%12,%13,%14,%15," \
        "%16,%17,%18,%19,%20,%21,%22,%23,%24,%25,%26,%27,%28,%29,%30,%31}, [%32];" \
        : "=r"((r)[0]),"=r"((r)[1]),"=r"((r)[2]),"=r"((r)[3]),"=r"((r)[4]),"=r"((r)[5]),"=r"((r)[6]),"=r"((r)[7]), \
          "=r"((r)[8]),"=r"((r)[9]),"=r"((r)[10]),"=r"((r)[11]),"=r"((r)[12]),"=r"((r)[13]),"=r"((r)[14]),"=r"((r)[15]), \
          "=r"((r)[16]),"=r"((r)[17]),"=r"((r)[18]),"=r"((r)[19]),"=r"((r)[20]),"=r"((r)[21]),"=r"((r)[22]),"=r"((r)[23]), \
          "=r"((r)[24]),"=r"((r)[25]),"=r"((r)[26]),"=r"((r)[27]),"=r"((r)[28]),"=r"((r)[29]),"=r"((r)[30]),"=r"((r)[31]) \
        : "r"(a))

static constexpr uint64_t DESC_BASE =
    (uint64_t(2) << 61) | (uint64_t(1) << 46) | (uint64_t(64) << 32) | (uint64_t(1) << 16);
#define MK_DESC(a) (DESC_BASE | ((uint64_t)((a) >> 4) & 0x3FFF))
#endif  // TC_OK

#define SWZ(o) ((o) ^ (((o) >> 3) & 0x70))

// ---------------- transpose ----------------
__global__ void transp(const float* __restrict__ in, float* __restrict__ out,
                       int R, int C, long sI, long sO) {
    __shared__ float t[32][33];
    in += (size_t)blockIdx.z * sI; out += (size_t)blockIdx.z * sO;
    int r0 = blockIdx.y * 32, c0 = blockIdx.x * 32;
    int x = threadIdx.x, y = threadIdx.y;
    for (int i = 0; i < 32; i += 8) t[y + i][x] = in[(size_t)(r0 + y + i) * C + c0 + x];
    __syncthreads();
    for (int i = 0; i < 32; i += 8) out[(size_t)(c0 + y + i) * R + r0 + x] = t[x][y + i];
}

// ---------------- generic split-tf32 GEMM (precombine / gate-hidden) ----------------
// packout != nullptr: also emit per-(z,kb) 64KB pre-swizzled tf32 blocks of C.
__global__ __launch_bounds__(256, 1) void tc_gemm(
    const float* __restrict__ A, const float* __restrict__ B, float* __restrict__ C,
    int M, int N, int K, int NT, long sA, long sB, long sC,
    const float* __restrict__ bias, int relu, uint32_t* __restrict__ packout)
{
    const int tid = threadIdx.x;
    A += (size_t)blockIdx.z * sA; B += (size_t)blockIdx.z * sB; C += (size_t)blockIdx.z * sC;
    const int bm = blockIdx.y * 128, bn = blockIdx.x * NT;
#if TC_OK
    extern __shared__ char sm[];
    const uint32_t sb = smem_u32(sm);
    const int wid = tid >> 5, lane = tid & 31;
    const uint32_t OAH = 1024, OAL = 17408, OBH = 33792, OBL = 66560, OMB = 16;

    if (wid == 0) TC_ALLOC(sb + 0, 256);
    if (tid == 0) MBAR_INIT(sb + OMB, 1);
    __syncthreads();
    uint32_t tb; asm volatile("ld.shared.b32 %0, [%1];" : "=r"(tb) : "r"(sb + 0));

    const uint32_t idesc = (1u << 4) | (2u << 7) | (2u << 10) | ((uint32_t)(NT >> 3) << 17) | (8u << 24);
    const int nks = K >> 5;

    for (int ks = 0; ks < nks; ks++) {
        const int k0 = ks << 5;
        if (ks > 0) MBAR_WAIT(sb + OMB, (ks - 1) & 1);
#pragma unroll 4
        for (int idx = tid; idx < 1024; idx += 256) {
            int n = idx >> 3, c4 = (idx & 7) * 4;
            float4 v = *(const float4*)(A + (size_t)(bm + n) * K + k0 + c4);
            uint32_t o = SWZ((uint32_t)(n * 128 + c4 * 4));
            float4 h, l;
            h.x = to_tf32(v.x); l.x = v.x - h.x;
            h.y = to_tf32(v.y); l.y = v.y - h.y;
            h.z = to_tf32(v.z); l.z = v.z - h.z;
            h.w = to_tf32(v.w); l.w = v.w - h.w;
            *(float4*)(sm + OAH + o) = h; *(float4*)(sm + OAL + o) = l;
        }
#pragma unroll 4
        for (int idx = tid; idx < NT * 8; idx += 256) {
            int n = idx >> 3, c4 = (idx & 7) * 4;
            float4 v = *(const float4*)(B + (size_t)(bn + n) * K + k0 + c4);
            uint32_t o = SWZ((uint32_t)(n * 128 + c4 * 4));
            float4 h, l;
            h.x = to_tf32(v.x); l.x = v.x - h.x;
            h.y = to_tf32(v.y); l.y = v.y - h.y;
            h.z = to_tf32(v.z); l.z = v.z - h.z;
            h.w = to_tf32(v.w); l.w = v.w - h.w;
            *(float4*)(sm + OBH + o) = h; *(float4*)(sm + OBL + o) = l;
        }
        FENCE_ASYNC();
        __syncthreads();
        if (wid == 0 && elect_one()) {
            uint64_t ah = MK_DESC(sb + OAH), al = MK_DESC(sb + OAL);
            uint64_t bh = MK_DESC(sb + OBH), bl = MK_DESC(sb + OBL);
#pragma unroll
            for (int k = 0; k < 4; k++) {
                mma_tf32(tb, ah + 2 * k, bh + 2 * k, idesc, (ks > 0) || (k > 0));
                mma_tf32(tb, ah + 2 * k, bl + 2 * k, idesc, 1);
                mma_tf32(tb, al + 2 * k, bh + 2 * k, idesc, 1);
            }
            TC_COMMIT(sb + OMB);
        }
        __syncthreads();
    }
    MBAR_WAIT(sb + OMB, (nks - 1) & 1);
    TC_FENCE_AFTER();

    const int row = bm + ((wid & 3) << 5) + lane;
    const int half = NT >> 1;
    for (int c = (wid >> 2) * half; c < (wid >> 2) * half + half; c += 32) {
        uint32_t rg[32];
        TC_LD_X32(rg, tb + c);
        TC_WAIT_LD();
        float v[32];
#pragma unroll
        for (int j = 0; j < 32; j++) v[j] = __uint_as_float(rg[j]);
        if (bias) {
#pragma unroll
            for (int j = 0; j < 32; j++) v[j] += __ldg(&bias[bn + c + j]);
        }
        if (relu) {
#pragma unroll
            for (int j = 0; j < 32; j++) v[j] = fmaxf(v[j], 0.0f);
        }
        float* op = C + (size_t)row * N + bn + c;
#pragma unroll
        for (int j = 0; j < 32; j += 4)
            *(float4*)(op + j) = make_float4(v[j], v[j + 1], v[j + 2], v[j + 3]);
        if (packout) {
            char* blk = (char*)(packout + (((size_t)blockIdx.z * 32 + (uint32_t)((bn + c) >> 5)) << 14));
            uint32_t rowo = (uint32_t)row * 128u;
#pragma unroll
            for (int j = 0; j < 8; j++)
                *(float4*)(blk + SWZ(rowo + j * 16)) =
                    make_float4(to_tf32(v[4 * j]), to_tf32(v[4 * j + 1]),
                                to_tf32(v[4 * j + 2]), to_tf32(v[4 * j + 3]));
        }
    }
    __syncthreads();
    if (tid == 0) MBAR_INVAL(sb + OMB);
    __syncthreads();
    if (wid == 0) { TC_RELINQ(); TC_DEALLOC(tb, 256); }
#else
    __shared__ float As[16][64];
    __shared__ float Bs[16][64];
    int tx = tid & 15, ty = tid >> 4;
    for (int smt = 0; smt < 2; smt++)
        for (int snt = 0; snt < NT / 64; snt++) {
            int m0 = bm + smt * 64, n0 = bn + snt * 64;
            float acc[4][4] = {};
            for (int k0 = 0; k0 < K; k0 += 16) {
                {
                    int r = tid >> 2, c = (tid & 3) * 4;
                    float4 v = *(const float4*)(A + (size_t)(m0 + r) * K + k0 + c);
                    As[c + 0][r] = v.x; As[c + 1][r] = v.y; As[c + 2][r] = v.z; As[c + 3][r] = v.w;
                    float4 w = *(const float4*)(B + (size_t)(n0 + r) * K + k0 + c);
                    Bs[c + 0][r] = w.x; Bs[c + 1][r] = w.y; Bs[c + 2][r] = w.z; Bs[c + 3][r] = w.w;
                }
                __syncthreads();
#pragma unroll
                for (int k = 0; k < 16; k++) {
                    float a[4], b[4];
                    *(float4*)&a[0] = *(const float4*)&As[k][ty * 4];
                    *(float4*)&b[0] = *(const float4*)&Bs[k][tx * 4];
#pragma unroll
                    for (int i = 0; i < 4; i++)
#pragma unroll
                        for (int j = 0; j < 4; j++) acc[i][j] += a[i] * b[j];
                }
                __syncthreads();
            }
#pragma unroll
            for (int i = 0; i < 4; i++)
#pragma unroll
                for (int j = 0; j < 4; j++) {
                    float v = acc[i][j];
                    int cc = n0 + tx * 4 + j;
                    if (bias) v += bias[cc];
                    if (relu) v = fmaxf(v, 0.0f);
                    C[(size_t)(m0 + ty * 4 + i) * N + cc] = v;
                }
            __syncthreads();
        }
#endif
}

// ---------------- bias: warp-per-output ----------------
__global__ __launch_bounds__(256) void bias_k2(
    const float* __restrict__ bv, const float* __restrict__ bvm,
    const float* __restrict__ bo, const float* __restrict__ WoT,
    const float* __restrict__ tmpT, float* __restrict__ bc)
{
    int o = blockIdx.x * 8 + (threadIdx.x >> 5);   // 4096 outputs
    int lane = threadIdx.x & 31;
    int e = o >> 9;
    const float* wr = WoT  + (size_t)o * NHH;
    const float* tr = tmpT + (size_t)o * NHH;
    const float* bvmE = bvm + e * NHH;
    const float* bvE  = bv + e * NHH;
    float s = 0.0f;
#pragma unroll
    for (int t = 0; t < 16; t++) {
        int g = lane + 32 * t;
        s += bvmE[g] * wr[g] + bvE[g] * tr[g];
    }
#pragma unroll
    for (int off = 16; off; off >>= 1) s += __shfl_xor_sync(0xFFFFFFFF, s, off);
    if (lane == 0) bc[o] = s + bo[o];
}

// ---------------- gate: warp-per-row, coalesced ----------------
__global__ __launch_bounds__(256) void gate_k2(
    const float* __restrict__ hidden, const float* __restrict__ Wg2,
    const float* __restrict__ bg2, float* __restrict__ gate)
{
    __shared__ float wg[NGH * NE];
    __shared__ float bg[NE];
    int tid = threadIdx.x;
#pragma unroll
    for (int i = 0; i < 4; i++) wg[tid + 256 * i] = Wg2[tid + 256 * i];
    if (tid < NE) bg[tid] = bg2[tid];
    __syncthreads();
    int b = blockIdx.x * 8 + (tid >> 5);
    int lane = tid & 31;
    const float* h = hidden + (size_t)b * NGH;
    float l[NE] = {};
#pragma unroll
    for (int t = 0; t < 4; t++) {
        int g = lane + 32 * t;
        float hv = h[g];
#pragma unroll
        for (int e = 0; e < NE; e++) l[e] += hv * wg[g * NE + e];
    }
#pragma unroll
    for (int off = 16; off; off >>= 1)
#pragma unroll
        for (int e = 0; e < NE; e++) l[e] += __shfl_xor_sync(0xFFFFFFFF, l[e], off);
    if (lane == 0) {
        float m = l[0] + bg[0];
#pragma unroll
        for (int e = 0; e < NE; e++) { l[e] += bg[e]; m = fmaxf(m, l[e]); }
        float s = 0.0f;
#pragma unroll
        for (int e = 0; e < NE; e++) { l[e] = __expf(l[e] - m); s += l[e]; }
        float inv = 1.0f / s;
        float* gp = gate + (size_t)b * NE;
        *(float4*)gp       = make_float4(l[0] * inv, l[1] * inv, l[2] * inv, l[3] * inv);
        *(float4*)(gp + 4) = make_float4(l[4] * inv, l[5] * inv, l[6] * inv, l[7] * inv);
    }
}

#if TC_OK
// SMEM layout for main_tc
#define M_OMD 16        // md[4]: 16,24,32,40
#define M_OBF 48        // bf[2]: 48,56
#define M_OBC 1024u
#define M_OG  17408u
#define M_OA  21504u    // 4 x 16384
#define M_OB  87040u    // 2 x 65536
#define M_SMEM 218112

static __device__ __forceinline__ void stage_A(
    char* sm, const float* __restrict__ freq, const float* gsm,
    int bm, int ks, int tid)
{
    const int e = ks >> 5, kb = ks & 31;
    const float* Ae = freq + ((size_t)e * NB + bm) * ND + (kb << 5);
    const uint32_t ab = M_OA + (uint32_t)(ks & 3) * 16384u;
#pragma unroll
    for (int it = 0; it < 4; it++) {
        int idx = tid + 256 * it;
        int n = idx >> 3, c4 = (idx & 7) * 4;
        float4 v = *(const float4*)(Ae + (size_t)n * ND + c4);
        float g = gsm[n * NE + e];
        v.x = to_tf32(v.x * g); v.y = to_tf32(v.y * g);
        v.z = to_tf32(v.z * g); v.w = to_tf32(v.w * g);
        *(float4*)(sm + ab + SWZ((uint32_t)(n * 128 + c4 * 4))) = v;
    }
}
#endif

// ---------------- main: tf32, A 4-deep / B 2-deep decoupled pipeline ----------------
__global__ __launch_bounds__(256, 1) void main_tc(
    const float* __restrict__ freq, const uint32_t* __restrict__ Wp,
    const float* __restrict__ WcT,  // SIMT fallback only
    const float* __restrict__ gate, const float* __restrict__ bc,
    float* __restrict__ out)
{
    const int tid = threadIdx.x;
    const int bm = blockIdx.x * 128;
#if TC_OK
    extern __shared__ char sm[];
    const uint32_t sb = smem_u32(sm);
    const int wid = tid >> 5, lane = tid & 31;

    if (wid == 0) TC_ALLOC(sb + 0, 512);
    if (tid == 0) {
#pragma unroll
        for (int i = 0; i < 4; i++) MBAR_INIT(sb + M_OMD + 8u * i, 1);
        MBAR_INIT(sb + M_OBF, 1);  MBAR_INIT(sb + M_OBF + 8, 1);
    }
    {
        float4* d = (float4*)(sm + M_OBC);
        const float4* s = (const float4*)bc;
#pragma unroll
        for (int i = 0; i < 4; i++) d[tid + 256 * i] = s[tid + 256 * i];
        ((float4*)(sm + M_OG))[tid] = ((const float4*)(gate + (size_t)bm * NE))[tid];
    }
    __syncthreads();
    uint32_t tb; asm volatile("ld.shared.b32 %0, [%1];" : "=r"(tb) : "r"(sb + 0));

    // kind::tf32, f32 accum, M=128, N=256
    const uint32_t idesc = (1u << 4) | (2u << 7) | (2u << 10) | (32u << 17) | (8u << 24);
    const int nks = NE * (ND >> 5);  // 256 steps of K=32
    const float* gsm = (const float*)(sm + M_OG);

    // prologue: B(0) copy; stage A(0), A(1)
    if (tid == 0) {
        MBAR_EXPECT_TX(sb + M_OBF, 65536u);
        BULK_G2S(sb + M_OB, (const char*)Wp, 65536u, sb + M_OBF);
    }
    stage_A(sm, freq, gsm, bm, 0, tid);
    stage_A(sm, freq, gsm, bm, 1, tid);
    FENCE_ASYNC();
    __syncthreads();

    for (int ks = 0; ks < nks; ks++) {
        // stage A(ks+2) — buffer freed by MMA(ks-2)
        if (ks + 2 < nks) {
            if (ks >= 2) MBAR_WAIT(sb + M_OMD + 8u * ((ks + 2) & 3), ((ks - 2) >> 2) & 1);
            stage_A(sm, freq, gsm, bm, ks + 2, tid);
            FENCE_ASYNC();
        }
        __syncthreads();
        // MMA(ks)
        if (wid == 0) {
            MBAR_WAIT(sb + M_OBF + 8u * (ks & 1), (ks >> 1) & 1);
            if (elect_one()) {
                uint64_t ad = MK_DESC(sb + M_OA + (uint32_t)(ks & 3) * 16384u);
                uint64_t bd = MK_DESC(sb + M_OB + (uint32_t)(ks & 1) * 65536u);
#pragma unroll
                for (int k = 0; k < 4; k++) {
                    uint32_t en = (ks > 0) || (k > 0);
                    mma_tf32(tb,       ad + 2 * k, bd + 2 * k,        idesc, en);
                    mma_tf32(tb + 256, ad + 2 * k, bd + 2048 + 2 * k, idesc, en);
                }
                TC_COMMIT(sb + M_OMD + 8u * (ks & 3));
            }
        }
        // prefetch B(ks+1): bbuf freed by MMA(ks-1)
        if (tid == 0 && ks + 1 < nks) {
            if (ks >= 1) MBAR_WAIT(sb + M_OMD + 8u * ((ks - 1) & 3), ((ks - 1) >> 2) & 1);
            uint32_t bful = sb + M_OBF + 8u * ((ks + 1) & 1);
            MBAR_EXPECT_TX(bful, 65536u);
            BULK_G2S(sb + M_OB + (uint32_t)((ks + 1) & 1) * 65536u,
                     (const char*)Wp + ((size_t)(ks + 1) << 16), 65536u, bful);
        }
    }
    // final drain: commit(nks-1) tracks all prior MMAs
    MBAR_WAIT(sb + M_OMD + 8u * ((nks - 1) & 3), ((nks - 1) >> 2) & 1);
    TC_FENCE_AFTER();

    const int rloc = ((wid & 3) << 5) + lane;
    const int grow = bm + rloc;
    const float* bcs = (const float*)(sm + M_OBC);
    float g[NE];
#pragma unroll
    for (int e = 0; e < NE; e++) g[e] = gsm[rloc * NE + e];
    const int ch = (wid >> 2) * 256;
    for (int c = ch; c < ch + 256; c += 32) {
        uint32_t rg[32];
        TC_LD_X32(rg, tb + c);
        TC_WAIT_LD();
        float v[32];
#pragma unroll
        for (int j = 0; j < 32; j++) {
            float bb = 0.0f;
#pragma unroll
            for (int e = 0; e < NE; e++) bb += g[e] * bcs[e * NHH + c + j];
            v[j] = __uint_as_float(rg[j]) + bb;
        }
        float* op = out + (size_t)grow * NHH + c;
#pragma unroll
        for (int j = 0; j < 32; j += 4)
            *(float4*)(op + j) = make_float4(v[j], v[j + 1], v[j + 2], v[j + 3]);
    }
    __syncthreads();
    if (tid == 0) {
#pragma unroll
        for (int i = 0; i < 4; i++) MBAR_INVAL(sb + M_OMD + 8u * i);
        MBAR_INVAL(sb + M_OBF); MBAR_INVAL(sb + M_OBF + 8);
    }
    __syncthreads();
    if (wid == 0) { TC_RELINQ(); TC_DEALLOC(tb, 512); }
#else
    // ---- SIMT fallback (portable pass) ----
    __shared__ float As[16][128];
    __shared__ float Bs[16][128];
    __shared__ float sg[128];
    int tx = tid & 15, ty = tid >> 4;
    for (int nc = 0; nc < 4; nc++) {
        int bn = nc * 128;
        float acc[8][8] = {};
        for (int e = 0; e < NE; e++) {
            __syncthreads();
            if (tid < 128) sg[tid] = gate[(size_t)(bm + tid) * NE + e];
            __syncthreads();
            const float* Ae = freq + ((size_t)e * NB + bm) * ND;
            const float* Be = WcT + (size_t)e * NHH * ND;
            for (int k0 = 0; k0 < ND; k0 += 16) {
#pragma unroll
                for (int p = 0; p < 2; p++) {
                    int r = (tid >> 2) + p * 64, c = (tid & 3) * 4;
                    float4 v = *(const float4*)(Ae + (size_t)r * ND + k0 + c);
                    float s = sg[r];
                    As[c + 0][r] = v.x * s; As[c + 1][r] = v.y * s;
                    As[c + 2][r] = v.z * s; As[c + 3][r] = v.w * s;
                    float4 w = *(const float4*)(Be + (size_t)(bn + r) * ND + k0 + c);
                    Bs[c + 0][r] = w.x; Bs[c + 1][r] = w.y; Bs[c + 2][r] = w.z; Bs[c + 3][r] = w.w;
                }
                __syncthreads();
#pragma unroll
                for (int k = 0; k < 16; k++) {
                    float a[8], b[8];
                    *(float4*)&a[0] = *(const float4*)&As[k][ty * 4];
                    *(float4*)&a[4] = *(const float4*)&As[k][64 + ty * 4];
                    *(float4*)&b[0] = *(const float4*)&Bs[k][tx * 4];
                    *(float4*)&b[4] = *(const float4*)&Bs[k][64 + tx * 4];
#pragma unroll
                    for (int i = 0; i < 8; i++)
#pragma unroll
                        for (int j = 0; j < 8; j++) acc[i][j] += a[i] * b[j];
                }
                __syncthreads();
            }
        }
        int rows[8], cols[8];
#pragma unroll
        for (int i = 0; i < 4; i++) {
            rows[i] = bm + ty * 4 + i; rows[i + 4] = bm + 64 + ty * 4 + i;
            cols[i] = bn + tx * 4 + i; cols[i + 4] = bn + 64 + tx * 4 + i;
        }
#pragma unroll
        for (int e = 0; e < NE; e++) {
            float gr[8], bv8[8];
#pragma unroll
            for (int i = 0; i < 8; i++) gr[i] = __ldg(&gate[(size_t)rows[i] * NE + e]);
#pragma unroll
            for (int j = 0; j < 8; j++) bv8[j] = __ldg(&bc[e * NHH + cols[j]]);
#pragma unroll
            for (int i = 0; i < 8; i++)
#pragma unroll
                for (int j = 0; j < 8; j++) acc[i][j] += gr[i] * bv8[j];
        }
#pragma unroll
        for (int i = 0; i < 8; i++) {
            *(float4*)(out + (size_t)rows[i] * NHH + cols[0]) =
                make_float4(acc[i][0], acc[i][1], acc[i][2], acc[i][3]);
            *(float4*)(out + (size_t)rows[i] * NHH + cols[4]) =
                make_float4(acc[i][4], acc[i][5], acc[i][6], acc[i][7]);
        }
    }
#endif
}

// ---------------- launcher ----------------
extern "C" void kernel_launch(void* const* d_in, const int* in_sizes, int n_in,
                              void* d_out, int out_size)
{
    const float* freq = (const float*)d_in[0];
    const float* sem  = (const float*)d_in[1];
    const float* Wv   = (const float*)d_in[6];
    const float* bv   = (const float*)d_in[7];
    const float* Wvm  = (const float*)d_in[12];
    const float* bvm  = (const float*)d_in[13];
    const float* Wo   = (const float*)d_in[14];
    const float* bo   = (const float*)d_in[15];
    const float* Wg1  = (const float*)d_in[16];
    const float* bg1  = (const float*)d_in[17];
    const float* Wg2  = (const float*)d_in[18];
    const float* bg2  = (const float*)d_in[19];
    float* out = (float*)d_out;

    float *tmpT, *WcT, *WoT, *Wg1T, *bc, *hidden, *gate;
    uint32_t* Wp;
    cudaGetSymbolAddress((void**)&tmpT,   g_tmpT);
    cudaGetSymbolAddress((void**)&WcT,    g_WcT);
    cudaGetSymbolAddress((void**)&Wp,     g_Wp);
    cudaGetSymbolAddress((void**)&WoT,    g_WoT);
    cudaGetSymbolAddress((void**)&Wg1T,   g_Wg1T);
    cudaGetSymbolAddress((void**)&bc,     g_bc);
    cudaGetSymbolAddress((void**)&hidden, g_hidden);
    cudaGetSymbolAddress((void**)&gate,   g_gate);

    cudaFuncSetAttribute(tc_gemm, cudaFuncAttributeMaxDynamicSharedMemorySize, 99328);
    cudaFuncSetAttribute(main_tc, cudaFuncAttributeMaxDynamicSharedMemorySize, 218112);

    transp<<<dim3(16, 16, NE), dim3(32, 8)>>>(Wo, WoT, NHH, NHH, (long)NHH * NHH, (long)NHH * NHH);
    transp<<<dim3(4, 32, 1), dim3(32, 8)>>>(Wg1, Wg1T, ND, NGH, 0, 0);

    // tmpT[e] = (Wvm@Wo)^T
    tc_gemm<<<dim3(2, 4, NE), 256, 99328>>>(
        WoT, Wvm, tmpT, NHH, NHH, NHH, 256,
        (long)NHH * NHH, (long)NHH * NHH, (long)NHH * NHH, nullptr, 0, nullptr);

    bias_k2<<<512, 256>>>(bv, bvm, bo, WoT, tmpT, bc);

    // WcT[e] = (Wv@tmp)^T  (f32, K-major) + fused pack into tf32 Wp
    tc_gemm<<<dim3(4, 4, NE), 256, 99328>>>(
        tmpT, Wv, WcT, NHH, ND, NHH, 256,
        (long)NHH * NHH, (long)ND * NHH, (long)NHH * ND, nullptr, 0, Wp);

    // hidden = relu(sem @ Wg1 + bg1)
    tc_gemm<<<dim3(1, NB / 128, 1), 256, 99328>>>(
        sem, Wg1T, hidden, NB, NGH, ND, 128, 0, 0, 0, bg1, 1, nullptr);

    gate_k2<<<NB / 8, 256>>>(hidden, Wg2, bg2, gate);

    main_tc<<<NB / 128, 256, 218112>>>(freq, Wp, WcT, gate, bc, out);
}

// round 15
// speedup vs baseline: 1.1734x; 1.1734x over previous
#include <cuda_runtime.h>
#include <cuda_bf16.h>
#include <cstdint>
#include <cstddef>

#define NE 8
#define NB 16384
#define ND 1024
#define NHH 512
#define NGH 128

#if defined(__CUDA_ARCH__) && (defined(__CUDA_ARCH_FEAT_SM103_ALL) || defined(__CUDA_ARCH_FEAT_SM100_ALL) || defined(__CUDA_ARCH_FEAT_SM101_ALL))
#define TC_OK 1
#else
#define TC_OK 0
#endif

// ---------------- device scratch ----------------
__device__ __align__(16) float g_tmpT[(size_t)NE * NHH * NHH];
__device__ __align__(16) float g_WcT[(size_t)NE * NHH * ND];      // f32 combined weight (K-major)
// Wp: per (e,kb) 64KB block = pre-swizzled SMEM image of the 512x(K=32) tf32 B tile
__device__ __align__(16) uint32_t g_Wp[(size_t)NE * NHH * ND];
__device__ __align__(16) float g_WoT[(size_t)NE * NHH * NHH];
__device__ __align__(16) float g_Wg1T[(size_t)NGH * ND];
__device__ __align__(16) float g_bc[NE * NHH];
__device__ __align__(16) float g_hidden[(size_t)NB * NGH];
__device__ __align__(16) float g_gate[NB * NE];

// ---------------- portable helpers ----------------
static __device__ __forceinline__ uint32_t smem_u32(const void* p) {
    uint32_t a;
    asm("{ .reg .u64 t; cvta.to.shared.u64 t, %1; cvt.u32.u64 %0, t; }" : "=r"(a) : "l"(p));
    return a;
}
static __device__ __forceinline__ float to_tf32(float x) {
    float r;
    asm("cvt.rna.tf32.f32 %0, %1;" : "=f"(r) : "f"(x));
    return r;
}

#if TC_OK
static __device__ __forceinline__ uint32_t elect_one() {
    uint32_t r;
    asm volatile("{ .reg .pred p; elect.sync _|p, 0xFFFFFFFF; selp.b32 %0,1,0,p; }" : "=r"(r));
    return r;
}
#define MBAR_INIT(a, c) asm volatile("mbarrier.init.shared.b64 [%0], %1;" ::"r"(a), "r"(c) : "memory")
#define MBAR_INVAL(a)   asm volatile("mbarrier.inval.shared.b64 [%0];" ::"r"(a) : "memory")
#define MBAR_EXPECT_TX(a, n) \
    asm volatile("mbarrier.arrive.expect_tx.shared.b64 _, [%0], %1;" ::"r"(a), "r"(n) : "memory")
#define MBAR_WAIT(a, ph) do { \
    uint32_t _m = (a), _p = (uint32_t)(ph), _d; \
    asm volatile("{ .reg .pred p; mbarrier.try_wait.parity.acquire.cta.shared::cta.b64 p, [%1], %2; selp.b32 %0,1,0,p; }" \
                 : "=r"(_d) : "r"(_m), "r"(_p) : "memory"); \
    if (!_d) { \
        asm volatile("{ .reg .pred P1; W%=: mbarrier.try_wait.parity.acquire.cta.shared::cta.b64 P1, [%0], %1, 0x989680; @P1 bra.uni D%=; bra.uni W%=; D%=: }" \
                     :: "r"(_m), "r"(_p) : "memory"); \
    } } while (0)
#define BULK_G2S(dst, src, bytes, mbar) \
    asm volatile("cp.async.bulk.shared::cluster.global.mbarrier::complete_tx::bytes [%0], [%1], %2, [%3];" \
                 :: "r"(dst), "l"(src), "r"(bytes), "r"(mbar) : "memory")
#define TC_ALLOC(sa, n)  asm volatile("tcgen05.alloc.cta_group::1.sync.aligned.shared::cta.b32 [%0], %1;" ::"r"(sa), "r"(n) : "memory")
#define TC_DEALLOC(t, n) asm volatile("tcgen05.dealloc.cta_group::1.sync.aligned.b32 %0, %1;" ::"r"(t), "r"(n))
#define TC_RELINQ()      asm volatile("tcgen05.relinquish_alloc_permit.cta_group::1.sync.aligned;")
#define TC_COMMIT(a)     asm volatile("tcgen05.commit.cta_group::1.mbarrier::arrive::one.shared::cluster.b64 [%0];" ::"r"(a) : "memory")
#define TC_WAIT_LD()     asm volatile("tcgen05.wait::ld.sync.aligned;" ::: "memory")
#define TC_FENCE_AFTER() asm volatile("tcgen05.fence::after_thread_sync;" ::: "memory")
#define FENCE_ASYNC()    asm volatile("fence.proxy.async.shared::cta;" ::: "memory")

static __device__ __forceinline__ void mma_tf32(uint32_t d, uint64_t ad, uint64_t bd,
                                                uint32_t idesc, uint32_t en) {
    asm volatile(
        "{ .reg .pred p; setp.ne.u32 p, %5, 0;\n\t"
        "tcgen05.mma.cta_group::1.kind::tf32 [%0], %1, %2, %3, {%4,%4,%4,%4}, p; }"
        :: "r"(d), "l"(ad), "l"(bd), "r"(idesc), "r"(0u), "r"(en) : "memory");
}
#define TC_LD_X32(r, a) \
    asm volatile("tcgen05.ld.sync.aligned.32x32b.x32.b32 " \
        "{%0,%1,%2,%3,%4,%5,%6,%7,%8,%9,%10,%11,%12,%13,%14,%15," \
        "%16,%17,%18,%19,%20,%21,%22,%23,%24,%25,%26,%27,%28,%29,%30,%31}, [%32];" \
        : "=r"((r)[0]),"=r"((r)[1]),"=r"((r)[2]),"=r"((r)[3]),"=r"((r)[4]),"=r"((r)[5]),"=r"((r)[6]),"=r"((r)[7]), \
          "=r"((r)[8]),"=r"((r)[9]),"=r"((r)[10]),"=r"((r)[11]),"=r"((r)[12]),"=r"((r)[13]),"=r"((r)[14]),"=r"((r)[15]), \
          "=r"((r)[16]),"=r"((r)[17]),"=r"((r)[18]),"=r"((r)[19]),"=r"((r)[20]),"=r"((r)[21]),"=r"((r)[22]),"=r"((r)[23]), \
          "=r"((r)[24]),"=r"((r)[25]),"=r"((r)[26]),"=r"((r)[27]),"=r"((r)[28]),"=r"((r)[29]),"=r"((r)[30]),"=r"((r)[31]) \
        : "r"(a))

static constexpr uint64_t DESC_BASE =
    (uint64_t(2) << 61) | (uint64_t(1) << 46) | (uint64_t(64) << 32) | (uint64_t(1) << 16);
#define MK_DESC(a) (DESC_BASE | ((uint64_t)((a) >> 4) & 0x3FFF))
#endif  // TC_OK

#define SWZ(o) ((o) ^ (((o) >> 3) & 0x70))

// ---------------- transpose ----------------
__global__ void transp(const float* __restrict__ in, float* __restrict__ out,
                       int R, int C, long sI, long sO) {
    __shared__ float t[32][33];
    in += (size_t)blockIdx.z * sI; out += (size_t)blockIdx.z * sO;
    int r0 = blockIdx.y * 32, c0 = blockIdx.x * 32;
    int x = threadIdx.x, y = threadIdx.y;
    for (int i = 0; i < 32; i += 8) t[y + i][x] = in[(size_t)(r0 + y + i) * C + c0 + x];
    __syncthreads();
    for (int i = 0; i < 32; i += 8) out[(size_t)(c0 + y + i) * R + r0 + x] = t[x][y + i];
}

// ---------------- generic split-tf32 GEMM (precombine / gate-hidden) ----------------
// packout != nullptr: also emit per-(z,kb) 64KB pre-swizzled tf32 blocks of C.
__global__ __launch_bounds__(256, 1) void tc_gemm(
    const float* __restrict__ A, const float* __restrict__ B, float* __restrict__ C,
    int M, int N, int K, int NT, long sA, long sB, long sC,
    const float* __restrict__ bias, int relu, uint32_t* __restrict__ packout)
{
    const int tid = threadIdx.x;
    A += (size_t)blockIdx.z * sA; B += (size_t)blockIdx.z * sB; C += (size_t)blockIdx.z * sC;
    const int bm = blockIdx.y * 128, bn = blockIdx.x * NT;
#if TC_OK
    extern __shared__ char sm[];
    const uint32_t sb = smem_u32(sm);
    const int wid = tid >> 5, lane = tid & 31;
    const uint32_t OAH = 1024, OAL = 17408, OBH = 33792, OBL = 66560, OMB = 16;

    if (wid == 0) TC_ALLOC(sb + 0, 256);
    if (tid == 0) MBAR_INIT(sb + OMB, 1);
    __syncthreads();
    uint32_t tb; asm volatile("ld.shared.b32 %0, [%1];" : "=r"(tb) : "r"(sb + 0));

    const uint32_t idesc = (1u << 4) | (2u << 7) | (2u << 10) | ((uint32_t)(NT >> 3) << 17) | (8u << 24);
    const int nks = K >> 5;

    for (int ks = 0; ks < nks; ks++) {
        const int k0 = ks << 5;
        if (ks > 0) MBAR_WAIT(sb + OMB, (ks - 1) & 1);
#pragma unroll 4
        for (int idx = tid; idx < 1024; idx += 256) {
            int n = idx >> 3, c4 = (idx & 7) * 4;
            float4 v = *(const float4*)(A + (size_t)(bm + n) * K + k0 + c4);
            uint32_t o = SWZ((uint32_t)(n * 128 + c4 * 4));
            float4 h, l;
            h.x = to_tf32(v.x); l.x = v.x - h.x;
            h.y = to_tf32(v.y); l.y = v.y - h.y;
            h.z = to_tf32(v.z); l.z = v.z - h.z;
            h.w = to_tf32(v.w); l.w = v.w - h.w;
            *(float4*)(sm + OAH + o) = h; *(float4*)(sm + OAL + o) = l;
        }
#pragma unroll 4
        for (int idx = tid; idx < NT * 8; idx += 256) {
            int n = idx >> 3, c4 = (idx & 7) * 4;
            float4 v = *(const float4*)(B + (size_t)(bn + n) * K + k0 + c4);
            uint32_t o = SWZ((uint32_t)(n * 128 + c4 * 4));
            float4 h, l;
            h.x = to_tf32(v.x); l.x = v.x - h.x;
            h.y = to_tf32(v.y); l.y = v.y - h.y;
            h.z = to_tf32(v.z); l.z = v.z - h.z;
            h.w = to_tf32(v.w); l.w = v.w - h.w;
            *(float4*)(sm + OBH + o) = h; *(float4*)(sm + OBL + o) = l;
        }
        FENCE_ASYNC();
        __syncthreads();
        if (wid == 0 && elect_one()) {
            uint64_t ah = MK_DESC(sb + OAH), al = MK_DESC(sb + OAL);
            uint64_t bh = MK_DESC(sb + OBH), bl = MK_DESC(sb + OBL);
#pragma unroll
            for (int k = 0; k < 4; k++) {
                mma_tf32(tb, ah + 2 * k, bh + 2 * k, idesc, (ks > 0) || (k > 0));
                mma_tf32(tb, ah + 2 * k, bl + 2 * k, idesc, 1);
                mma_tf32(tb, al + 2 * k, bh + 2 * k, idesc, 1);
            }
            TC_COMMIT(sb + OMB);
        }
        __syncthreads();
    }
    MBAR_WAIT(sb + OMB, (nks - 1) & 1);
    TC_FENCE_AFTER();

    const int row = bm + ((wid & 3) << 5) + lane;
    const int half = NT >> 1;
    for (int c = (wid >> 2) * half; c < (wid >> 2) * half + half; c += 32) {
        uint32_t rg[32];
        TC_LD_X32(rg, tb + c);
        TC_WAIT_LD();
        float v[32];
#pragma unroll
        for (int j = 0; j < 32; j++) v[j] = __uint_as_float(rg[j]);
        if (bias) {
#pragma unroll
            for (int j = 0; j < 32; j++) v[j] += __ldg(&bias[bn + c + j]);
        }
        if (relu) {
#pragma unroll
            for (int j = 0; j < 32; j++) v[j] = fmaxf(v[j], 0.0f);
        }
        float* op = C + (size_t)row * N + bn + c;
#pragma unroll
        for (int j = 0; j < 32; j += 4)
            *(float4*)(op + j) = make_float4(v[j], v[j + 1], v[j + 2], v[j + 3]);
        if (packout) {
            char* blk = (char*)(packout + (((size_t)blockIdx.z * 32 + (uint32_t)((bn + c) >> 5)) << 14));
            uint32_t rowo = (uint32_t)row * 128u;
#pragma unroll
            for (int j = 0; j < 8; j++)
                *(float4*)(blk + SWZ(rowo + j * 16)) =
                    make_float4(to_tf32(v[4 * j]), to_tf32(v[4 * j + 1]),
                                to_tf32(v[4 * j + 2]), to_tf32(v[4 * j + 3]));
        }
    }
    __syncthreads();
    if (tid == 0) MBAR_INVAL(sb + OMB);
    __syncthreads();
    if (wid == 0) { TC_RELINQ(); TC_DEALLOC(tb, 256); }
#else
    __shared__ float As[16][64];
    __shared__ float Bs[16][64];
    int tx = tid & 15, ty = tid >> 4;
    for (int smt = 0; smt < 2; smt++)
        for (int snt = 0; snt < NT / 64; snt++) {
            int m0 = bm + smt * 64, n0 = bn + snt * 64;
            float acc[4][4] = {};
            for (int k0 = 0; k0 < K; k0 += 16) {
                {
                    int r = tid >> 2, c = (tid & 3) * 4;
                    float4 v = *(const float4*)(A + (size_t)(m0 + r) * K + k0 + c);
                    As[c + 0][r] = v.x; As[c + 1][r] = v.y; As[c + 2][r] = v.z; As[c + 3][r] = v.w;
                    float4 w = *(const float4*)(B + (size_t)(n0 + r) * K + k0 + c);
                    Bs[c + 0][r] = w.x; Bs[c + 1][r] = w.y; Bs[c + 2][r] = w.z; Bs[c + 3][r] = w.w;
                }
                __syncthreads();
#pragma unroll
                for (int k = 0; k < 16; k++) {
                    float a[4], b[4];
                    *(float4*)&a[0] = *(const float4*)&As[k][ty * 4];
                    *(float4*)&b[0] = *(const float4*)&Bs[k][tx * 4];
#pragma unroll
                    for (int i = 0; i < 4; i++)
#pragma unroll
                        for (int j = 0; j < 4; j++) acc[i][j] += a[i] * b[j];
                }
                __syncthreads();
            }
#pragma unroll
            for (int i = 0; i < 4; i++)
#pragma unroll
                for (int j = 0; j < 4; j++) {
                    float v = acc[i][j];
                    int cc = n0 + tx * 4 + j;
                    if (bias) v += bias[cc];
                    if (relu) v = fmaxf(v, 0.0f);
                    C[(size_t)(m0 + ty * 4 + i) * N + cc] = v;
                }
            __syncthreads();
        }
#endif
}

// ---------------- bias: warp-per-output ----------------
__global__ __launch_bounds__(256) void bias_k2(
    const float* __restrict__ bv, const float* __restrict__ bvm,
    const float* __restrict__ bo, const float* __restrict__ WoT,
    const float* __restrict__ tmpT, float* __restrict__ bc)
{
    int o = blockIdx.x * 8 + (threadIdx.x >> 5);   // 4096 outputs
    int lane = threadIdx.x & 31;
    int e = o >> 9;
    const float* wr = WoT  + (size_t)o * NHH;
    const float* tr = tmpT + (size_t)o * NHH;
    const float* bvmE = bvm + e * NHH;
    const float* bvE  = bv + e * NHH;
    float s = 0.0f;
#pragma unroll
    for (int t = 0; t < 16; t++) {
        int g = lane + 32 * t;
        s += bvmE[g] * wr[g] + bvE[g] * tr[g];
    }
#pragma unroll
    for (int off = 16; off; off >>= 1) s += __shfl_xor_sync(0xFFFFFFFF, s, off);
    if (lane == 0) bc[o] = s + bo[o];
}

// ---------------- gate: warp-per-row, coalesced ----------------
__global__ __launch_bounds__(256) void gate_k2(
    const float* __restrict__ hidden, const float* __restrict__ Wg2,
    const float* __restrict__ bg2, float* __restrict__ gate)
{
    __shared__ float wg[NGH * NE];
    __shared__ float bg[NE];
    int tid = threadIdx.x;
#pragma unroll
    for (int i = 0; i < 4; i++) wg[tid + 256 * i] = Wg2[tid + 256 * i];
    if (tid < NE) bg[tid] = bg2[tid];
    __syncthreads();
    int b = blockIdx.x * 8 + (tid >> 5);
    int lane = tid & 31;
    const float* h = hidden + (size_t)b * NGH;
    float l[NE] = {};
#pragma unroll
    for (int t = 0; t < 4; t++) {
        int g = lane + 32 * t;
        float hv = h[g];
#pragma unroll
        for (int e = 0; e < NE; e++) l[e] += hv * wg[g * NE + e];
    }
#pragma unroll
    for (int off = 16; off; off >>= 1)
#pragma unroll
        for (int e = 0; e < NE; e++) l[e] += __shfl_xor_sync(0xFFFFFFFF, l[e], off);
    if (lane == 0) {
        float m = l[0] + bg[0];
#pragma unroll
        for (int e = 0; e < NE; e++) { l[e] += bg[e]; m = fmaxf(m, l[e]); }
        float s = 0.0f;
#pragma unroll
        for (int e = 0; e < NE; e++) { l[e] = __expf(l[e] - m); s += l[e]; }
        float inv = 1.0f / s;
        float* gp = gate + (size_t)b * NE;
        *(float4*)gp       = make_float4(l[0] * inv, l[1] * inv, l[2] * inv, l[3] * inv);
        *(float4*)(gp + 4) = make_float4(l[4] * inv, l[5] * inv, l[6] * inv, l[7] * inv);
    }
}

#if TC_OK
// SMEM layout for main_tc (230400 bytes dynamic)
#define M_OMD 16u       // md[4]: 16,24,32,40
#define M_OBF 48u       // bf[3]: 48,56,64
#define M_OA  1024u     // 2 x 16384  (A buffers; bc staged here after mainloop)
#define M_OB  33792u    // 3 x 65536
#define M_SMEM 230400

static __device__ __forceinline__ void stage_A(
    char* sm, const float* __restrict__ freq, const float* __restrict__ gate,
    int bm, int ks, int tid, int abuf)
{
    const int e = ks >> 5, kb = ks & 31;
    const float* Ae = freq + ((size_t)e * NB + bm) * ND + (kb << 5);
    const uint32_t ab = M_OA + (uint32_t)abuf * 16384u;
#pragma unroll
    for (int it = 0; it < 4; it++) {
        int idx = tid + 256 * it;
        int n = idx >> 3, c4 = (idx & 7) * 4;
        float4 v = *(const float4*)(Ae + (size_t)n * ND + c4);
        float g = __ldg(&gate[(size_t)(bm + n) * NE + e]);
        v.x = to_tf32(v.x * g); v.y = to_tf32(v.y * g);
        v.z = to_tf32(v.z * g); v.w = to_tf32(v.w * g);
        *(float4*)(sm + ab + SWZ((uint32_t)(n * 128 + c4 * 4))) = v;
    }
}
#endif

// ---------------- main: tf32, 2 K-steps per iteration, B 3-ring ----------------
__global__ __launch_bounds__(256, 1) void main_tc(
    const float* __restrict__ freq, const uint32_t* __restrict__ Wp,
    const float* __restrict__ WcT,  // SIMT fallback only
    const float* __restrict__ gate, const float* __restrict__ bc,
    float* __restrict__ out)
{
    const int tid = threadIdx.x;
    const int bm = blockIdx.x * 128;
#if TC_OK
    extern __shared__ char sm[];
    const uint32_t sb = smem_u32(sm);
    const int wid = tid >> 5, lane = tid & 31;

    if (wid == 0) TC_ALLOC(sb + 0, 512);
    if (tid == 0) {
#pragma unroll
        for (int i = 0; i < 4; i++) MBAR_INIT(sb + M_OMD + 8u * i, 1);
#pragma unroll
        for (int i = 0; i < 3; i++) MBAR_INIT(sb + M_OBF + 8u * i, 1);
    }
    __syncthreads();
    uint32_t tb; asm volatile("ld.shared.b32 %0, [%1];" : "=r"(tb) : "r"(sb + 0));

    // kind::tf32, f32 accum, M=128, N=256
    const uint32_t idesc = (1u << 4) | (2u << 7) | (2u << 10) | (32u << 17) | (8u << 24);
    const int nks = NE * (ND >> 5);  // 256 steps of K=32
    const int nit = nks >> 1;        // 128 iterations, 2 steps each

    // prologue: B(0)->slot0, B(1)->slot1
    if (tid == 0) {
#pragma unroll
        for (int j = 0; j < 2; j++) {
            MBAR_EXPECT_TX(sb + M_OBF + 8u * j, 65536u);
            BULK_G2S(sb + M_OB + (uint32_t)j * 65536u,
                     (const char*)Wp + ((size_t)j << 16), 65536u, sb + M_OBF + 8u * j);
        }
    }

    for (int i = 0; i < nit; i++) {
        const int a = 2 * i, b = a + 1;
        // A-buffer reuse: previous iteration's MMAs (steps a-2, b-2) must be done.
        // commit(b-2) tracks all prior MMAs -> one wait covers both buffers.
        if (i >= 1) MBAR_WAIT(sb + M_OMD + 8u * ((b - 2) & 3), ((b - 2) >> 2) & 1);
        stage_A(sm, freq, gate, bm, a, tid, 0);
        stage_A(sm, freq, gate, bm, b, tid, 1);
        FENCE_ASYNC();
        __syncthreads();
        if (wid == 0) {
            // step a
            MBAR_WAIT(sb + M_OBF + 8u * (a % 3), (a / 3) & 1);
            if (elect_one()) {
                uint64_t ad = MK_DESC(sb + M_OA);
                uint64_t bd = MK_DESC(sb + M_OB + (uint32_t)(a % 3) * 65536u);
#pragma unroll
                for (int k = 0; k < 4; k++) {
                    uint32_t en = (a > 0) || (k > 0);
                    mma_tf32(tb,       ad + 2 * k, bd + 2 * k,        idesc, en);
                    mma_tf32(tb + 256, ad + 2 * k, bd + 2048 + 2 * k, idesc, en);
                }
                TC_COMMIT(sb + M_OMD + 8u * (a & 3));
            }
            // step b
            MBAR_WAIT(sb + M_OBF + 8u * (b % 3), (b / 3) & 1);
            if (elect_one()) {
                uint64_t ad = MK_DESC(sb + M_OA + 16384u);
                uint64_t bd = MK_DESC(sb + M_OB + (uint32_t)(b % 3) * 65536u);
#pragma unroll
                for (int k = 0; k < 4; k++) {
                    mma_tf32(tb,       ad + 2 * k, bd + 2 * k,        idesc, 1);
                    mma_tf32(tb + 256, ad + 2 * k, bd + 2048 + 2 * k, idesc, 1);
                }
                TC_COMMIT(sb + M_OMD + 8u * (b & 3));
            }
        }
        // prefetch B(a+2), B(b+2); slot j%3 freed when MMA(j-3) done
        if (tid == 0) {
#pragma unroll
            for (int d = 2; d < 4; d++) {
                int j = a + d;
                if (j < nks) {
                    if (j >= 3) MBAR_WAIT(sb + M_OMD + 8u * ((j - 3) & 3), ((j - 3) >> 2) & 1);
                    uint32_t bful = sb + M_OBF + 8u * (j % 3);
                    MBAR_EXPECT_TX(bful, 65536u);
                    BULK_G2S(sb + M_OB + (uint32_t)(j % 3) * 65536u,
                             (const char*)Wp + ((size_t)j << 16), 65536u, bful);
                }
            }
        }
    }
    // drain: commit(nks-1) tracks all prior MMAs
    MBAR_WAIT(sb + M_OMD + 8u * ((nks - 1) & 3), ((nks - 1) >> 2) & 1);
    TC_FENCE_AFTER();
    __syncthreads();
    {   // stage bc (8x512 f32 = 16KB) into dead A-buffer space
        float4* d = (float4*)(sm + M_OA);
        const float4* s = (const float4*)bc;
#pragma unroll
        for (int i2 = 0; i2 < 4; i2++) d[tid + 256 * i2] = s[tid + 256 * i2];
    }
    __syncthreads();

    const int rloc = ((wid & 3) << 5) + lane;
    const int grow = bm + rloc;
    const float* bcs = (const float*)(sm + M_OA);
    float g[NE];
#pragma unroll
    for (int e = 0; e < NE; e++) g[e] = __ldg(&gate[(size_t)grow * NE + e]);
    const int ch = (wid >> 2) * 256;
    for (int c = ch; c < ch + 256; c += 32) {
        uint32_t rg[32];
        TC_LD_X32(rg, tb + c);
        TC_WAIT_LD();
        float v[32];
#pragma unroll
        for (int j = 0; j < 32; j++) {
            float bb = 0.0f;
#pragma unroll
            for (int e = 0; e < NE; e++) bb += g[e] * bcs[e * NHH + c + j];
            v[j] = __uint_as_float(rg[j]) + bb;
        }
        float* op = out + (size_t)grow * NHH + c;
#pragma unroll
        for (int j = 0; j < 32; j += 4)
            *(float4*)(op + j) = make_float4(v[j], v[j + 1], v[j + 2], v[j + 3]);
    }
    __syncthreads();
    if (tid == 0) {
#pragma unroll
        for (int i2 = 0; i2 < 4; i2++) MBAR_INVAL(sb + M_OMD + 8u * i2);
#pragma unroll
        for (int i2 = 0; i2 < 3; i2++) MBAR_INVAL(sb + M_OBF + 8u * i2);
    }
    __syncthreads();
    if (wid == 0) { TC_RELINQ(); TC_DEALLOC(tb, 512); }
#else
    // ---- SIMT fallback (portable pass) ----
    __shared__ float As[16][128];
    __shared__ float Bs[16][128];
    __shared__ float sg[128];
    int tx = tid & 15, ty = tid >> 4;
    for (int nc = 0; nc < 4; nc++) {
        int bn = nc * 128;
        float acc[8][8] = {};
        for (int e = 0; e < NE; e++) {
            __syncthreads();
            if (tid < 128) sg[tid] = gate[(size_t)(bm + tid) * NE + e];
            __syncthreads();
            const float* Ae = freq + ((size_t)e * NB + bm) * ND;
            const float* Be = WcT + (size_t)e * NHH * ND;
            for (int k0 = 0; k0 < ND; k0 += 16) {
#pragma unroll
                for (int p = 0; p < 2; p++) {
                    int r = (tid >> 2) + p * 64, c = (tid & 3) * 4;
                    float4 v = *(const float4*)(Ae + (size_t)r * ND + k0 + c);
                    float s = sg[r];
                    As[c + 0][r] = v.x * s; As[c + 1][r] = v.y * s;
                    As[c + 2][r] = v.z * s; As[c + 3][r] = v.w * s;
                    float4 w = *(const float4*)(Be + (size_t)(bn + r) * ND + k0 + c);
                    Bs[c + 0][r] = w.x; Bs[c + 1][r] = w.y; Bs[c + 2][r] = w.z; Bs[c + 3][r] = w.w;
                }
                __syncthreads();
#pragma unroll
                for (int k = 0; k < 16; k++) {
                    float a[8], b[8];
                    *(float4*)&a[0] = *(const float4*)&As[k][ty * 4];
                    *(float4*)&a[4] = *(const float4*)&As[k][64 + ty * 4];
                    *(float4*)&b[0] = *(const float4*)&Bs[k][tx * 4];
                    *(float4*)&b[4] = *(const float4*)&Bs[k][64 + tx * 4];
#pragma unroll
                    for (int i = 0; i < 8; i++)
#pragma unroll
                        for (int j = 0; j < 8; j++) acc[i][j] += a[i] * b[j];
                }
                __syncthreads();
            }
        }
        int rows[8], cols[8];
#pragma unroll
        for (int i = 0; i < 4; i++) {
            rows[i] = bm + ty * 4 + i; rows[i + 4] = bm + 64 + ty * 4 + i;
            cols[i] = bn + tx * 4 + i; cols[i + 4] = bn + 64 + tx * 4 + i;
        }
#pragma unroll
        for (int e = 0; e < NE; e++) {
            float gr[8], bv8[8];
#pragma unroll
            for (int i = 0; i < 8; i++) gr[i] = __ldg(&gate[(size_t)rows[i] * NE + e]);
#pragma unroll
            for (int j = 0; j < 8; j++) bv8[j] = __ldg(&bc[e * NHH + cols[j]]);
#pragma unroll
            for (int i = 0; i < 8; i++)
#pragma unroll
                for (int j = 0; j < 8; j++) acc[i][j] += gr[i] * bv8[j];
        }
#pragma unroll
        for (int i = 0; i < 8; i++) {
            *(float4*)(out + (size_t)rows[i] * NHH + cols[0]) =
                make_float4(acc[i][0], acc[i][1], acc[i][2], acc[i][3]);
            *(float4*)(out + (size_t)rows[i] * NHH + cols[4]) =
                make_float4(acc[i][4], acc[i][5], acc[i][6], acc[i][7]);
        }
    }
#endif
}

// ---------------- launcher ----------------
extern "C" void kernel_launch(void* const* d_in, const int* in_sizes, int n_in,
                              void* d_out, int out_size)
{
    const float* freq = (const float*)d_in[0];
    const float* sem  = (const float*)d_in[1];
    const float* Wv   = (const float*)d_in[6];
    const float* bv   = (const float*)d_in[7];
    const float* Wvm  = (const float*)d_in[12];
    const float* bvm  = (const float*)d_in[13];
    const float* Wo   = (const float*)d_in[14];
    const float* bo   = (const float*)d_in[15];
    const float* Wg1  = (const float*)d_in[16];
    const float* bg1  = (const float*)d_in[17];
    const float* Wg2  = (const float*)d_in[18];
    const float* bg2  = (const float*)d_in[19];
    float* out = (float*)d_out;

    float *tmpT, *WcT, *WoT, *Wg1T, *bc, *hidden, *gate;
    uint32_t* Wp;
    cudaGetSymbolAddress((void**)&tmpT,   g_tmpT);
    cudaGetSymbolAddress((void**)&WcT,    g_WcT);
    cudaGetSymbolAddress((void**)&Wp,     g_Wp);
    cudaGetSymbolAddress((void**)&WoT,    g_WoT);
    cudaGetSymbolAddress((void**)&Wg1T,   g_Wg1T);
    cudaGetSymbolAddress((void**)&bc,     g_bc);
    cudaGetSymbolAddress((void**)&hidden, g_hidden);
    cudaGetSymbolAddress((void**)&gate,   g_gate);

    cudaFuncSetAttribute(tc_gemm, cudaFuncAttributeMaxDynamicSharedMemorySize, 99328);
    cudaFuncSetAttribute(main_tc, cudaFuncAttributeMaxDynamicSharedMemorySize, 230400);

    transp<<<dim3(16, 16, NE), dim3(32, 8)>>>(Wo, WoT, NHH, NHH, (long)NHH * NHH, (long)NHH * NHH);
    transp<<<dim3(4, 32, 1), dim3(32, 8)>>>(Wg1, Wg1T, ND, NGH, 0, 0);

    // tmpT[e] = (Wvm@Wo)^T
    tc_gemm<<<dim3(2, 4, NE), 256, 99328>>>(
        WoT, Wvm, tmpT, NHH, NHH, NHH, 256,
        (long)NHH * NHH, (long)NHH * NHH, (long)NHH * NHH, nullptr, 0, nullptr);

    bias_k2<<<512, 256>>>(bv, bvm, bo, WoT, tmpT, bc);

    // WcT[e] = (Wv@tmp)^T  (f32, K-major) + fused pack into tf32 Wp
    tc_gemm<<<dim3(4, 4, NE), 256, 99328>>>(
        tmpT, Wv, WcT, NHH, ND, NHH, 256,
        (long)NHH * NHH, (long)ND * NHH, (long)NHH * ND, nullptr, 0, Wp);

    // hidden = relu(sem @ Wg1 + bg1)
    tc_gemm<<<dim3(1, NB / 128, 1), 256, 99328>>>(
        sem, Wg1T, hidden, NB, NGH, ND, 128, 0, 0, 0, bg1, 1, nullptr);

    gate_k2<<<NB / 8, 256>>>(hidden, Wg2, bg2, gate);

    main_tc<<<NB / 128, 256, 230400>>>(freq, Wp, WcT, gate, bc, out);
}